// round 1
// baseline (speedup 1.0000x reference)
#include <cuda_runtime.h>

// ---------------------------------------------------------------------------
// WaveletConv: 8-level DWT (fixed 10-tap filters) + 8-level inverse DWT
// (per-channel 32-tap filters). 128 independent channels -> 1 CTA per channel.
// ---------------------------------------------------------------------------

#define NCH      128
#define TLEN     131072
#define NTHREADS 256
#define FCHUNK   4096   // forward outputs per smem chunk
#define ICT      4096   // inverse t-pairs per smem chunk
#define SMEM_F   8464   // total smem floats (forward uses 2*FCHUNK+9, inverse 2x(ICT+15))

// Level sizes: L[0]=131072, L[l] = L[l-1]/2 + 1
__device__ __constant__ int c_LSZ[9]  = {131072, 65537, 32769, 16385, 8193, 4097, 2049, 1025, 513};
// hi-coefficient offsets (cumulative sizes of LSZ[1..8]); total = 130568
__device__ __constant__ int c_HOFF[8] = {0, 65537, 98306, 114691, 122884, 126981, 129030, 130055};

// Fixed analysis filters (compile-time constants -> FFMA with immediate)
__device__ __forceinline__ float WLO(int k) {
    constexpr float w[10] = {0.003335725285001549f, -0.012580751999015526f,
        -0.006241490213011705f, 0.07757149384006515f, -0.03224486958502952f,
        -0.24229488706619015f, 0.13842814590110342f, 0.7243085284385744f,
        0.6038292697974729f, 0.160102397974125f};
    return w[k];
}
__device__ __forceinline__ float WHI(int k) {
    constexpr float w[10] = {-0.160102397974125f, 0.6038292697974729f,
        -0.7243085284385744f, 0.13842814590110342f, 0.24229488706619015f,
        -0.03224486958502952f, -0.07757149384006515f, -0.006241490213011705f,
        0.012580751999015526f, 0.003335725285001549f};
    return w[k];
}

// Static scratch (allocation-free rule): ~117 MB total
__device__ float g_hi[NCH * 130568];   // all hi coefficients, per channel
__device__ float g_bufA[NCH * 32772];  // ping-pong A (max 32769)
__device__ float g_bufB[NCH * 65540];  // ping-pong B (max 65537)

// ---------------------------------------------------------------------------
// Forward level: lo_out[j] = sum_k in[2j-5+k]*WLO[k]; hi_out[j] likewise.
// Input staged into smem (zero-padded) in chunks; taps read as float2 LDS.64.
// ---------------------------------------------------------------------------
__device__ __forceinline__ void fwd_level(
    const float* __restrict__ in, int Lin,
    float* __restrict__ lo, float* __restrict__ hi, int Lout,
    float* s_in)
{
    const int tid = threadIdx.x;
    for (int j0 = 0; j0 < Lout; j0 += FCHUNK) {
        const int jend = min(j0 + FCHUNK, Lout);
        const int base = 2 * j0 - 5;                 // global idx of s_in[0]
        const int cnt  = 2 * (jend - j0) + 9;        // floats needed
        for (int q = tid; q < cnt; q += NTHREADS) {
            const int idx = base + q;
            s_in[q] = (idx >= 0 && idx < Lin) ? in[idx] : 0.0f;
        }
        __syncthreads();
        const float2* s2 = reinterpret_cast<const float2*>(s_in);
        for (int j = j0 + tid; j < jend; j += NTHREADS) {
            const int jj = j - j0;                   // s_in[2*jj] == in[2j-5]
            float alo = 0.0f, ahi = 0.0f;
            #pragma unroll
            for (int k = 0; k < 5; k++) {
                const float2 v = s2[jj + k];
                alo = fmaf(v.x, WLO(2 * k),     alo);
                alo = fmaf(v.y, WLO(2 * k + 1), alo);
                ahi = fmaf(v.x, WHI(2 * k),     ahi);
                ahi = fmaf(v.y, WHI(2 * k + 1), ahi);
            }
            lo[j] = alo;
            hi[j] = ahi;
        }
        __syncthreads();
    }
}

// ---------------------------------------------------------------------------
// Inverse level (transposed conv as two 16-tap FIRs):
//   out[2t]   = sum_j prev[t-7+j]*cl[2j+1] + hi[t-7+j]*ch[2j+1]
//   out[2t+1] = sum_j prev[t-7+j]*cl[2j]   + hi[t-7+j]*ch[2j]
// prev/hi staged into smem (zero-padded halo) per chunk; coeffs in registers.
// ---------------------------------------------------------------------------
__device__ __forceinline__ void inv_level(
    const float* __restrict__ prev, const float* __restrict__ hi,
    int L, float* __restrict__ out, int Nout,
    const float* cl, const float* ch,   // local (register) arrays of 32
    float* s_prev, float* s_hi)
{
    const int tid  = threadIdx.x;
    const int tmax = (Nout + 1) >> 1;   // t values with out[2t] valid
    for (int tc0 = 0; tc0 < tmax; tc0 += ICT) {
        const int tc1   = min(tc0 + ICT, tmax);
        const int mbase = tc0 - 7;
        const int cnt   = (tc1 - tc0) + 15;
        for (int q = tid; q < cnt; q += NTHREADS) {
            const int m = mbase + q;
            const bool ok = (m >= 0) && (m < L);
            s_prev[q] = ok ? prev[m] : 0.0f;
            s_hi[q]   = ok ? hi[m]   : 0.0f;
        }
        __syncthreads();
        for (int t = tc0 + tid; t < tc1; t += NTHREADS) {
            const int p = t - tc0;      // s_prev[p] == prev[t-7]
            float a0p = 0.f, a0h = 0.f, a1p = 0.f, a1h = 0.f;  // 4 dep chains
            #pragma unroll
            for (int j = 0; j < 16; j++) {
                const float pv = s_prev[p + j];
                const float hv = s_hi[p + j];
                a0p = fmaf(pv, cl[2 * j + 1], a0p);
                a0h = fmaf(hv, ch[2 * j + 1], a0h);
                a1p = fmaf(pv, cl[2 * j],     a1p);
                a1h = fmaf(hv, ch[2 * j],     a1h);
            }
            const float o0 = a0p + a0h;
            const float o1 = a1p + a1h;
            const int n = 2 * t;
            if (n + 1 < Nout) {
                *reinterpret_cast<float2*>(&out[n]) = make_float2(o0, o1);
            } else {
                out[n] = o0;
            }
        }
        __syncthreads();
    }
}

// ---------------------------------------------------------------------------
__global__ void __launch_bounds__(NTHREADS)
wavelet_kernel(const float* __restrict__ x, const float* __restrict__ filt,
               float* __restrict__ out)
{
    __shared__ __align__(16) float s_mem[SMEM_F];
    const int c = blockIdx.x;

    const float* xrow = x + (size_t)c * TLEN;
    float* bufA  = g_bufA + (size_t)c * 32772;
    float* bufB  = g_bufB + (size_t)c * 65540;
    float* hibse = g_hi   + (size_t)c * 130568;

    // ---- forward DWT: level l reads lo_{l-1}, writes lo_l + hi_l ----
    {
        const float* cur = xrow;
        int Lin = TLEN;
        for (int l = 1; l <= 8; l++) {
            const int Lout = Lin / 2 + 1;
            float* lo = (l & 1) ? bufB : bufA;
            fwd_level(cur, Lin, lo, hibse + c_HOFF[l - 1], Lout, s_mem);
            cur = lo;
            Lin = Lout;
        }
    }

    // ---- inverse DWT: i = 7..0; ping-pong A<->B, last level -> d_out ----
    float* s_prev = s_mem;
    float* s_hi   = s_mem + (ICT + 32);
    for (int i = 7; i >= 0; i--) {
        // per-channel, per-level 32-tap filters into registers
        const float* flo = filt + (((size_t)c * 8 + (size_t)i) * 2) * 32;
        float cl[32], ch[32];
        #pragma unroll
        for (int k = 0; k < 32; k++) { cl[k] = flo[k]; ch[k] = flo[32 + k]; }

        const int   L    = c_LSZ[i + 1];
        const float* pv  = (i & 1) ? bufA : bufB;           // prev buffer
        const float* hv  = hibse + c_HOFF[i];               // stored hi_{i+1}
        float* dst;
        int Nout;
        if (i == 0) { dst = out + (size_t)c * TLEN; Nout = TLEN; }  // drop last
        else        { dst = (i & 1) ? bufB : bufA;  Nout = 2 * L - 1; }

        inv_level(pv, hv, L, dst, Nout, cl, ch, s_prev, s_hi);
    }
}

// ---------------------------------------------------------------------------
extern "C" void kernel_launch(void* const* d_in, const int* in_sizes, int n_in,
                              void* d_out, int out_size)
{
    const float* x    = (const float*)d_in[0];
    const float* filt = (const float*)d_in[1];
    // robust input identification: x has 16.7M elements, filters 65536
    if (n_in >= 2 && in_sizes[0] < in_sizes[1]) {
        x    = (const float*)d_in[1];
        filt = (const float*)d_in[0];
    }
    wavelet_kernel<<<NCH, NTHREADS>>>(x, filt, (float*)d_out);
}

// round 2
// speedup vs baseline: 2.3860x; 2.3860x over previous
#include <cuda_runtime.h>

// ---------------------------------------------------------------------------
// WaveletConv, multi-launch version: 16 kernels (8 forward DWT levels with
// fixed 10-tap filters, 8 inverse levels with per-channel 32-tap filters).
// Each level is fully parallel over (channel, position) -> thousands of CTAs.
// Inverse uses packed f32x2 FMA and 4-way register blocking.
// ---------------------------------------------------------------------------

#define NCH      128
#define TLEN     131072
#define NTHREADS 256
#define FCH      2048   // forward outputs per CTA
#define TCH      1024   // inverse t-positions per CTA (4 per thread)

// Level sizes: L[0]=131072, L[l] = L[l-1]/2 + 1
__device__ __constant__ int c_LSZ[9]  = {131072, 65537, 32769, 16385, 8193, 4097, 2049, 1025, 513};
__device__ __constant__ int c_HOFF[8] = {0, 65537, 98306, 114691, 122884, 126981, 129030, 130055};

__device__ __constant__ float c_WLO[10] = {0.003335725285001549f, -0.012580751999015526f,
    -0.006241490213011705f, 0.07757149384006515f, -0.03224486958502952f,
    -0.24229488706619015f, 0.13842814590110342f, 0.7243085284385744f,
    0.6038292697974729f, 0.160102397974125f};
__device__ __constant__ float c_WHI[10] = {-0.160102397974125f, 0.6038292697974729f,
    -0.7243085284385744f, 0.13842814590110342f, 0.24229488706619015f,
    -0.03224486958502952f, -0.07757149384006515f, -0.006241490213011705f,
    0.012580751999015526f, 0.003335725285001549f};

// Static scratch (allocation-free rule)
__device__ float g_hi[NCH * 130568];   // all forward hi coefficients
__device__ float g_bufA[NCH * 32772];  // ping-pong A
__device__ float g_bufB[NCH * 65540];  // ping-pong B

// ---- packed f32x2 helpers --------------------------------------------------
typedef unsigned long long ull;

__device__ __forceinline__ ull pk2(float lo, float hi) {
    ull r;
    asm("mov.b64 %0, {%1, %2};" : "=l"(r) : "f"(lo), "f"(hi));
    return r;
}
__device__ __forceinline__ ull bcast2(float v) {
    ull r;
    asm("mov.b64 %0, {%1, %1};" : "=l"(r) : "f"(v));
    return r;
}
__device__ __forceinline__ void ffma2(ull& d, ull a, ull b) {
    asm("fma.rn.f32x2 %0, %1, %2, %3;" : "=l"(d) : "l"(a), "l"(b), "l"(d));
}
__device__ __forceinline__ void add2(ull& d, ull a, ull b) {
    asm("add.rn.f32x2 %0, %1, %2;" : "=l"(d) : "l"(a), "l"(b));
}
__device__ __forceinline__ void unpk2(float& lo, float& hi, ull r) {
    asm("mov.b64 {%0, %1}, %2;" : "=f"(lo), "=f"(hi) : "l"(r));
}

// ---------------------------------------------------------------------------
// Forward level l (1..8): lo[j] = sum_k in[2j-5+k]*WLO[k]; hi[j] likewise.
// grid = (ceil(Lout/FCH), NCH). Packed: lo-lane = lo output, hi-lane = hi.
// ---------------------------------------------------------------------------
__global__ void __launch_bounds__(NTHREADS)
fwd_kernel(const float* __restrict__ x, int l)
{
    __shared__ __align__(16) float s_in[2 * FCH + 12];
    const int ch  = blockIdx.y;
    const int tid = threadIdx.x;
    const int Lin  = c_LSZ[l - 1];
    const int Lout = c_LSZ[l];

    const float* __restrict__ in;
    if (l == 1) in = x + (size_t)ch * TLEN;
    else        in = ((l - 1) & 1) ? g_bufB + (size_t)ch * 65540
                                   : g_bufA + (size_t)ch * 32772;
    float* __restrict__ lo = (l & 1) ? g_bufB + (size_t)ch * 65540
                                     : g_bufA + (size_t)ch * 32772;
    float* __restrict__ hi = g_hi + (size_t)ch * 130568 + c_HOFF[l - 1];

    const int j0 = blockIdx.x * FCH;
    if (j0 >= Lout) return;
    const int jend = min(j0 + FCH, Lout);
    const int cw   = jend - j0;
    const int base = 2 * j0 - 5;
    const int cnt  = 2 * cw + 9;

    for (int q = tid; q < cnt; q += NTHREADS) {
        const int idx = base + q;
        s_in[q] = (idx >= 0 && idx < Lin) ? in[idx] : 0.0f;
    }
    __syncthreads();

    // packed filter coefficients: lane-lo = WLO[k], lane-hi = WHI[k]
    ull W2[10];
    #pragma unroll
    for (int k = 0; k < 10; k++) W2[k] = pk2(c_WLO[k], c_WHI[k]);

    const float2* s2 = reinterpret_cast<const float2*>(s_in);
    for (int j = j0 + tid; j < jend; j += NTHREADS) {
        const int jj = j - j0;                 // s_in[2*jj] == in[2j-5]
        ull acc = 0ull;                        // {0.f, 0.f}
        #pragma unroll
        for (int k = 0; k < 5; k++) {
            const float2 v = s2[jj + k];
            ffma2(acc, bcast2(v.x), W2[2 * k]);
            ffma2(acc, bcast2(v.y), W2[2 * k + 1]);
        }
        float alo, ahi;
        unpk2(alo, ahi, acc);
        lo[j] = alo;
        hi[j] = ahi;
    }
}

// ---------------------------------------------------------------------------
// Inverse level i (7..0):
//   out[2t]   = sum_j prev[t-7+j]*cl[2j+1] + hi[t-7+j]*ch[2j+1]   (j=0..15)
//   out[2t+1] = sum_j prev[t-7+j]*cl[2j]   + hi[t-7+j]*ch[2j]
// Packed accumulators: lane-lo = even output, lane-hi = odd output.
// Each thread computes 4 consecutive t (streaming window, taps jj..jj-3).
// grid = (ceil(tmax/TCH), NCH).
// ---------------------------------------------------------------------------
__global__ void __launch_bounds__(NTHREADS)
inv_kernel(const float* __restrict__ filt, float* __restrict__ outbase, int i)
{
    __shared__ __align__(16) float s_prev[TCH + 24];
    __shared__ __align__(16) float s_hi[TCH + 24];

    const int ch  = blockIdx.y;
    const int tid = threadIdx.x;
    const int L    = c_LSZ[i + 1];
    const int Nout = (i == 0) ? TLEN : 2 * L - 1;
    const int tmax = (Nout + 1) >> 1;

    const float* __restrict__ prev = (i & 1) ? g_bufA + (size_t)ch * 32772
                                             : g_bufB + (size_t)ch * 65540;
    const float* __restrict__ hv   = g_hi + (size_t)ch * 130568 + c_HOFF[i];
    float* __restrict__ out = (i == 0) ? outbase + (size_t)ch * TLEN
                            : ((i & 1) ? g_bufB + (size_t)ch * 65540
                                       : g_bufA + (size_t)ch * 32772);

    const int tc0 = blockIdx.x * TCH;
    if (tc0 >= tmax) return;

    // stage prev/hi chunk with zero-padded halo: s_prev[q] = prev[tc0-7+q]
    const int mbase = tc0 - 7;
    #pragma unroll 2
    for (int q = tid; q < TCH + 20; q += NTHREADS) {
        const int m  = mbase + q;
        const bool ok = (m >= 0) && (m < L);
        s_prev[q] = ok ? prev[m] : 0.0f;
        s_hi[q]   = ok ? hv[m]   : 0.0f;
    }

    // per-channel per-level packed filters: PL[j]={cl[2j+1],cl[2j]}, PH likewise
    const float2* f2 = reinterpret_cast<const float2*>(filt + ((size_t)ch * 8 + (size_t)i) * 64);
    ull PL[16], PH[16];
    #pragma unroll
    for (int j = 0; j < 16; j++) {
        const float2 a = f2[j];       // {cl[2j], cl[2j+1]}
        const float2 b = f2[16 + j];  // {ch[2j], ch[2j+1]}
        PL[j] = pk2(a.y, a.x);
        PH[j] = pk2(b.y, b.x);
    }
    __syncthreads();

    // thread handles t0..t0+3, window positions p..p+19 (float2 aligned, p even)
    const int p = 4 * tid;
    const float2* sp2 = reinterpret_cast<const float2*>(s_prev + p);
    const float2* sh2 = reinterpret_cast<const float2*>(s_hi + p);

    ull accp[4] = {0ull, 0ull, 0ull, 0ull};
    ull acch[4] = {0ull, 0ull, 0ull, 0ull};

    #pragma unroll
    for (int m = 0; m < 10; m++) {
        const float2 pv = sp2[m];
        const float2 hvv = sh2[m];
        const ull pvx = bcast2(pv.x),  pvy = bcast2(pv.y);
        const ull hvx = bcast2(hvv.x), hvy = bcast2(hvv.y);
        #pragma unroll
        for (int k = 0; k < 4; k++) {
            const int j0 = 2 * m - k;      // tap for element .x
            const int j1 = 2 * m + 1 - k;  // tap for element .y
            if (j0 >= 0 && j0 < 16) { ffma2(accp[k], pvx, PL[j0]); ffma2(acch[k], hvx, PH[j0]); }
            if (j1 >= 0 && j1 < 16) { ffma2(accp[k], pvy, PL[j1]); ffma2(acch[k], hvy, PH[j1]); }
        }
    }

    const int t0 = tc0 + p;
    #pragma unroll
    for (int k = 0; k < 4; k++) {
        ull res;
        add2(res, accp[k], acch[k]);
        float oe, oo;
        unpk2(oe, oo, res);
        const int n = 2 * (t0 + k);
        if (n + 1 < Nout) {
            *reinterpret_cast<float2*>(&out[n]) = make_float2(oe, oo);
        } else if (n < Nout) {
            out[n] = oe;
        }
    }
}

// ---------------------------------------------------------------------------
extern "C" void kernel_launch(void* const* d_in, const int* in_sizes, int n_in,
                              void* d_out, int out_size)
{
    const float* x    = (const float*)d_in[0];
    const float* filt = (const float*)d_in[1];
    if (n_in >= 2 && in_sizes[0] < in_sizes[1]) {   // robust input order
        x    = (const float*)d_in[1];
        filt = (const float*)d_in[0];
    }
    float* out = (float*)d_out;

    static const int LSZ[9] = {131072, 65537, 32769, 16385, 8193, 4097, 2049, 1025, 513};

    // forward DWT: 8 launches
    for (int l = 1; l <= 8; l++) {
        const int Lout = LSZ[l];
        dim3 grid((Lout + FCH - 1) / FCH, NCH);
        fwd_kernel<<<grid, NTHREADS>>>(x, l);
    }
    // inverse DWT: 8 launches
    for (int i = 7; i >= 0; i--) {
        const int L    = LSZ[i + 1];
        const int Nout = (i == 0) ? TLEN : 2 * L - 1;
        const int tmax = (Nout + 1) >> 1;
        dim3 grid((tmax + TCH - 1) / TCH, NCH);
        inv_kernel<<<grid, NTHREADS>>>(filt, out, i);
    }
}

// round 3
// speedup vs baseline: 2.9105x; 1.2198x over previous
#include <cuda_runtime.h>

// ---------------------------------------------------------------------------
// WaveletConv: 7 launches.
//   fwd levels 1-3   : wide kernels (grid ~ position x channel)
//   fwd 4-8 + inv 7-3: ONE fused per-channel kernel, all data in smem
//   inv levels 2-0   : wide kernels
// Packed f32x2 FMA throughout; float4 staging/stores on wide kernels.
// ---------------------------------------------------------------------------

#define NCH      128
#define TLEN     131072
#define NTHREADS 256
#define FNT      512    // fused kernel threads
#define FCH      2048   // forward outputs per CTA
#define TCH      1024   // inverse t-positions per CTA (4 per thread)

// Level sizes: L[0]=131072, L[l] = L[l-1]/2 + 1
__device__ __constant__ int c_LSZ[9]  = {131072, 65537, 32769, 16385, 8193, 4097, 2049, 1025, 513};
// hi offsets padded to multiples of 4 floats (16B) for vector loads
__device__ __constant__ int c_HOFF[8] = {0, 65540, 98312, 114700, 122896, 126996, 129048, 130076};
#define HI_STRIDE 130592

__device__ __constant__ float c_WLO[10] = {0.003335725285001549f, -0.012580751999015526f,
    -0.006241490213011705f, 0.07757149384006515f, -0.03224486958502952f,
    -0.24229488706619015f, 0.13842814590110342f, 0.7243085284385744f,
    0.6038292697974729f, 0.160102397974125f};
__device__ __constant__ float c_WHI[10] = {-0.160102397974125f, 0.6038292697974729f,
    -0.7243085284385744f, 0.13842814590110342f, 0.24229488706619015f,
    -0.03224486958502952f, -0.07757149384006515f, -0.006241490213011705f,
    0.012580751999015526f, 0.003335725285001549f};

// Static scratch (allocation-free rule)
__device__ __align__(16) float g_hi[NCH * HI_STRIDE];
__device__ __align__(16) float g_bufA[NCH * 32772];
__device__ __align__(16) float g_bufB[NCH * 65540];

// ---- packed f32x2 helpers --------------------------------------------------
typedef unsigned long long ull;

__device__ __forceinline__ ull pk2(float lo, float hi) {
    ull r; asm("mov.b64 %0, {%1, %2};" : "=l"(r) : "f"(lo), "f"(hi)); return r;
}
__device__ __forceinline__ ull bcast2(float v) {
    ull r; asm("mov.b64 %0, {%1, %1};" : "=l"(r) : "f"(v)); return r;
}
__device__ __forceinline__ void ffma2(ull& d, ull a, ull b) {
    asm("fma.rn.f32x2 %0, %1, %2, %3;" : "=l"(d) : "l"(a), "l"(b), "l"(d));
}
__device__ __forceinline__ void add2(ull& d, ull a, ull b) {
    asm("add.rn.f32x2 %0, %1, %2;" : "=l"(d) : "l"(a), "l"(b));
}
__device__ __forceinline__ void unpk2(float& lo, float& hi, ull r) {
    asm("mov.b64 {%0, %1}, %2;" : "=f"(lo), "=f"(hi) : "l"(r));
}

// shared inverse compute: 4 consecutive t, packed even/odd outputs
// sp2/sh2 point (float2-aligned) at prev[t0-7] / hi[t0-7]
__device__ __forceinline__ void inv_compute4(const float2* sp2, const float2* sh2,
                                             const ull* PL, const ull* PH,
                                             ull* accp, ull* acch)
{
    #pragma unroll
    for (int k = 0; k < 4; k++) { accp[k] = 0ull; acch[k] = 0ull; }
    #pragma unroll
    for (int m = 0; m < 10; m++) {
        const float2 pv = sp2[m];
        const float2 hv = sh2[m];
        const ull pvx = bcast2(pv.x), pvy = bcast2(pv.y);
        const ull hvx = bcast2(hv.x), hvy = bcast2(hv.y);
        #pragma unroll
        for (int k = 0; k < 4; k++) {
            const int j0 = 2 * m - k;
            const int j1 = 2 * m + 1 - k;
            if (j0 >= 0 && j0 < 16) { ffma2(accp[k], pvx, PL[j0]); ffma2(acch[k], hvx, PH[j0]); }
            if (j1 >= 0 && j1 < 16) { ffma2(accp[k], pvy, PL[j1]); ffma2(acch[k], hvy, PH[j1]); }
        }
    }
}

// ---------------------------------------------------------------------------
// Wide forward level l (1..3)
// ---------------------------------------------------------------------------
__global__ void __launch_bounds__(NTHREADS)
fwd_kernel(const float* __restrict__ x, int l)
{
    __shared__ __align__(16) float s_in[2 * FCH + 12];
    const int ch  = blockIdx.y;
    const int tid = threadIdx.x;
    const int Lin  = c_LSZ[l - 1];
    const int Lout = c_LSZ[l];

    const float* __restrict__ in;
    if (l == 1) in = x + (size_t)ch * TLEN;
    else        in = ((l - 1) & 1) ? g_bufB + (size_t)ch * 65540
                                   : g_bufA + (size_t)ch * 32772;
    float* __restrict__ lo = (l & 1) ? g_bufB + (size_t)ch * 65540
                                     : g_bufA + (size_t)ch * 32772;
    float* __restrict__ hi = g_hi + (size_t)ch * HI_STRIDE + c_HOFF[l - 1];

    const int j0 = blockIdx.x * FCH;
    if (j0 >= Lout) return;
    const int jend = min(j0 + FCH, Lout);
    const int base = 2 * j0 - 5;
    const int cnt  = 2 * (jend - j0) + 9;

    const bool interior = (jend == j0 + FCH) && (base >= 0) && (base + cnt <= Lin);
    if (interior) {
        // base == 3 (mod 4); q == 1 (mod 4) is 16B-aligned. cnt = 4105 exactly.
        if (tid == 0) s_in[0] = in[base];
        for (int q = 1 + 4 * tid; q + 3 < cnt; q += 4 * NTHREADS) {
            const float4 v = *reinterpret_cast<const float4*>(in + base + q);
            s_in[q] = v.x; s_in[q + 1] = v.y; s_in[q + 2] = v.z; s_in[q + 3] = v.w;
        }
    } else {
        for (int q = tid; q < cnt; q += NTHREADS) {
            const int idx = base + q;
            s_in[q] = (idx >= 0 && idx < Lin) ? in[idx] : 0.0f;
        }
    }
    __syncthreads();

    ull W2[10];
    #pragma unroll
    for (int k = 0; k < 10; k++) W2[k] = pk2(c_WLO[k], c_WHI[k]);

    const float2* s2 = reinterpret_cast<const float2*>(s_in);
    for (int j = j0 + tid; j < jend; j += NTHREADS) {
        const int jj = j - j0;
        ull acc = 0ull;
        #pragma unroll
        for (int k = 0; k < 5; k++) {
            const float2 v = s2[jj + k];
            ffma2(acc, bcast2(v.x), W2[2 * k]);
            ffma2(acc, bcast2(v.y), W2[2 * k + 1]);
        }
        float alo, ahi;
        unpk2(alo, ahi, acc);
        lo[j] = alo;
        hi[j] = ahi;
    }
}

// ---------------------------------------------------------------------------
// Wide inverse level i (2..0)
// ---------------------------------------------------------------------------
__global__ void __launch_bounds__(NTHREADS)
inv_kernel(const float* __restrict__ filt, float* __restrict__ outbase, int i)
{
    __shared__ __align__(16) float s_prev[TCH + 24];
    __shared__ __align__(16) float s_hi[TCH + 24];

    const int ch  = blockIdx.y;
    const int tid = threadIdx.x;
    const int L    = c_LSZ[i + 1];
    const int Nout = (i == 0) ? TLEN : 2 * L - 1;
    const int tmax = (Nout + 1) >> 1;

    const float* __restrict__ prev = (i & 1) ? g_bufA + (size_t)ch * 32772
                                             : g_bufB + (size_t)ch * 65540;
    const float* __restrict__ hv   = g_hi + (size_t)ch * HI_STRIDE + c_HOFF[i];
    float* __restrict__ out = (i == 0) ? outbase + (size_t)ch * TLEN
                            : ((i & 1) ? g_bufB + (size_t)ch * 65540
                                       : g_bufA + (size_t)ch * 32772);

    const int tc0 = blockIdx.x * TCH;
    if (tc0 >= tmax) return;
    const int tc1   = min(tc0 + TCH, tmax);
    const int mbase = tc0 - 7;
    const int cnt   = (tc1 - tc0) + 20;

    const bool interior = (tc1 == tc0 + TCH) && (mbase >= 0) && (mbase + cnt <= L);
    if (interior) {
        // mbase == 1 (mod 4); q == 3 (mod 4) aligned. cnt = 1044.
        if (tid < 3) { s_prev[tid] = prev[mbase + tid]; s_hi[tid] = hv[mbase + tid]; }
        if (tid == 3) { s_prev[cnt - 1] = prev[mbase + cnt - 1]; s_hi[cnt - 1] = hv[mbase + cnt - 1]; }
        for (int q = 3 + 4 * tid; q + 3 < cnt; q += 4 * NTHREADS) {
            const float4 a = *reinterpret_cast<const float4*>(prev + mbase + q);
            const float4 b = *reinterpret_cast<const float4*>(hv + mbase + q);
            s_prev[q] = a.x; s_prev[q+1] = a.y; s_prev[q+2] = a.z; s_prev[q+3] = a.w;
            s_hi[q]   = b.x; s_hi[q+1]   = b.y; s_hi[q+2]   = b.z; s_hi[q+3]   = b.w;
        }
    } else {
        for (int q = tid; q < cnt; q += NTHREADS) {
            const int m  = mbase + q;
            const bool ok = (m >= 0) && (m < L);
            s_prev[q] = ok ? prev[m] : 0.0f;
            s_hi[q]   = ok ? hv[m]   : 0.0f;
        }
    }

    // packed per-channel filters: PL[j]={cl[2j+1],cl[2j]}, PH likewise
    const float2* f2 = reinterpret_cast<const float2*>(filt + ((size_t)ch * 8 + (size_t)i) * 64);
    ull PL[16], PH[16];
    #pragma unroll
    for (int j = 0; j < 16; j++) {
        const float2 a = f2[j];
        const float2 b = f2[16 + j];
        PL[j] = pk2(a.y, a.x);
        PH[j] = pk2(b.y, b.x);
    }
    __syncthreads();

    const int p  = 4 * tid;
    const int t0 = tc0 + p;
    if (t0 >= tmax) return;

    ull accp[4], acch[4];
    inv_compute4(reinterpret_cast<const float2*>(s_prev + p),
                 reinterpret_cast<const float2*>(s_hi + p), PL, PH, accp, acch);

    float o[8];
    #pragma unroll
    for (int k = 0; k < 4; k++) {
        ull r; add2(r, accp[k], acch[k]);
        unpk2(o[2 * k], o[2 * k + 1], r);
    }
    const int n0 = 2 * t0;   // == 0 (mod 8) -> 32B aligned
    if (n0 + 7 < Nout && t0 + 3 < tmax) {
        *reinterpret_cast<float4*>(out + n0)     = make_float4(o[0], o[1], o[2], o[3]);
        *reinterpret_cast<float4*>(out + n0 + 4) = make_float4(o[4], o[5], o[6], o[7]);
    } else {
        #pragma unroll
        for (int k = 0; k < 4; k++) {
            if (t0 + k < tmax) {
                const int n = n0 + 2 * k;
                if (n < Nout)     out[n]     = o[2 * k];
                if (n + 1 < Nout) out[n + 1] = o[2 * k + 1];
            }
        }
    }
}

// ---------------------------------------------------------------------------
// Fused middle kernel: fwd levels 4-8 + inverse levels 7-3, all in smem.
// One CTA per channel. Buffers (region base, data at base+7, pads zeroed):
//   X: 0..16400   Y: 16400..24608   H4..H8 follow. Total 40560 floats.
// ---------------------------------------------------------------------------
#define OX  0
#define OY  16400
#define OH4 24608
#define OH5 32816
#define OH6 36928
#define OH7 38992
#define OH8 40032
#define SM_FLOATS 40560

__device__ __forceinline__ void fused_fwd_level(
    const float* inb, float* lob, float* hib, int Lout, int tid, const ull* W2)
{
    const float* ind = inb + 7;
    float* lod = lob + 7;
    float* hid = hib + 7;
    for (int j = tid; j < Lout; j += FNT) {
        ull acc = 0ull;
        #pragma unroll
        for (int k = 0; k < 10; k++)
            ffma2(acc, bcast2(ind[2 * j - 5 + k]), W2[k]);
        float alo, ahi;
        unpk2(alo, ahi, acc);
        lod[j] = alo;
        hid[j] = ahi;
    }
    if (tid < 7)        { lob[tid] = 0.f; hib[tid] = 0.f; }
    else if (tid < 15)  { lod[Lout + tid - 7] = 0.f; hid[Lout + tid - 7] = 0.f; }
}

__device__ __forceinline__ void fused_load_filters(
    const float* __restrict__ filt, int ch, int i, ull* PL, ull* PH)
{
    const float2* f2 = reinterpret_cast<const float2*>(filt + ((size_t)ch * 8 + (size_t)i) * 64);
    #pragma unroll
    for (int j = 0; j < 16; j++) {
        const float2 a = f2[j];
        const float2 b = f2[16 + j];
        PL[j] = pk2(a.y, a.x);
        PH[j] = pk2(b.y, b.x);
    }
}

// inverse level into smem buffer
__device__ __forceinline__ void fused_inv_level(
    const float* prevb, const float* hib, float* outb, int L,
    const ull* PL, const ull* PH, int tid)
{
    float* outd = outb + 7;
    const int tmax = L;          // Nout = 2L-1
    for (int tb = 0; tb < tmax; tb += 4 * FNT) {
        const int t0 = tb + 4 * tid;
        if (t0 < tmax) {
            ull accp[4], acch[4];
            inv_compute4(reinterpret_cast<const float2*>(prevb + t0),
                         reinterpret_cast<const float2*>(hib + t0), PL, PH, accp, acch);
            #pragma unroll
            for (int k = 0; k < 4; k++) {
                if (t0 + k < tmax) {
                    ull r; add2(r, accp[k], acch[k]);
                    float oe, oo;
                    unpk2(oe, oo, r);
                    outd[2 * (t0 + k)]     = oe;
                    outd[2 * (t0 + k) + 1] = oo;  // may hit pad slot; zeroed below
                }
            }
        }
    }
    __syncthreads();
    const int Nout = 2 * L - 1;
    if (tid < 7)       outb[tid] = 0.f;
    else if (tid < 15) outd[Nout + tid - 7] = 0.f;
}

__global__ void __launch_bounds__(FNT)
mid_kernel(const float* __restrict__ filt)
{
    extern __shared__ __align__(16) float s[];
    const int ch  = blockIdx.x;
    const int tid = threadIdx.x;

    ull W2[10];
    #pragma unroll
    for (int k = 0; k < 10; k++) W2[k] = pk2(c_WLO[k], c_WHI[k]);

    // stage lo_3 (16385 floats) from g_bufB into X
    {
        const float* __restrict__ src = g_bufB + (size_t)ch * 65540;
        float* dst = s + OX + 7;
        for (int q = 4 * tid; q + 3 < 16385; q += 4 * FNT) {
            const float4 v = *reinterpret_cast<const float4*>(src + q);
            dst[q] = v.x; dst[q + 1] = v.y; dst[q + 2] = v.z; dst[q + 3] = v.w;
        }
        if (tid == 0) dst[16384] = src[16384];
        if (tid < 7)       s[OX + tid] = 0.f;
        else if (tid < 15) dst[16385 + tid - 7] = 0.f;
    }
    __syncthreads();

    // forward levels 4..8 (X->Y->X->Y->...; hi into H regions)
    fused_fwd_level(s + OX, s + OY, s + OH4, 8193, tid, W2);  __syncthreads(); // L4
    fused_fwd_level(s + OY, s + OX, s + OH5, 4097, tid, W2);  __syncthreads(); // L5
    fused_fwd_level(s + OX, s + OY, s + OH6, 2049, tid, W2);  __syncthreads(); // L6
    fused_fwd_level(s + OY, s + OX, s + OH7, 1025, tid, W2);  __syncthreads(); // L7
    fused_fwd_level(s + OX, s + OY, s + OH8,  513, tid, W2);  __syncthreads(); // L8

    // inverse levels 7..4 in smem
    ull PL[16], PH[16];
    fused_load_filters(filt, ch, 7, PL, PH);
    fused_inv_level(s + OY, s + OH8, s + OX,  513, PL, PH, tid); __syncthreads();
    fused_load_filters(filt, ch, 6, PL, PH);
    fused_inv_level(s + OX, s + OH7, s + OY, 1025, PL, PH, tid); __syncthreads();
    fused_load_filters(filt, ch, 5, PL, PH);
    fused_inv_level(s + OY, s + OH6, s + OX, 2049, PL, PH, tid); __syncthreads();
    fused_load_filters(filt, ch, 4, PL, PH);
    fused_inv_level(s + OX, s + OH5, s + OY, 4097, PL, PH, tid); __syncthreads();

    // inverse level 3: smem -> global (prev_3 into g_bufB, consumed by inv i=2)
    fused_load_filters(filt, ch, 3, PL, PH);
    {
        const float* prevb = s + OY;
        const float* hib   = s + OH4;
        float* __restrict__ out = g_bufB + (size_t)ch * 65540;
        const int L = 8193, tmax = 8193, Nout = 16385;
        for (int tb = 0; tb < tmax; tb += 4 * FNT) {
            const int t0 = tb + 4 * tid;
            if (t0 >= tmax) break;
            ull accp[4], acch[4];
            inv_compute4(reinterpret_cast<const float2*>(prevb + t0),
                         reinterpret_cast<const float2*>(hib + t0), PL, PH, accp, acch);
            float o[8];
            #pragma unroll
            for (int k = 0; k < 4; k++) {
                ull r; add2(r, accp[k], acch[k]);
                unpk2(o[2 * k], o[2 * k + 1], r);
            }
            const int n0 = 2 * t0;
            if (n0 + 7 < Nout && t0 + 3 < tmax) {
                *reinterpret_cast<float4*>(out + n0)     = make_float4(o[0], o[1], o[2], o[3]);
                *reinterpret_cast<float4*>(out + n0 + 4) = make_float4(o[4], o[5], o[6], o[7]);
            } else {
                #pragma unroll
                for (int k = 0; k < 4; k++) {
                    if (t0 + k < tmax) {
                        const int n = n0 + 2 * k;
                        if (n < Nout)     out[n]     = o[2 * k];
                        if (n + 1 < Nout) out[n + 1] = o[2 * k + 1];
                    }
                }
            }
        }
        (void)L;
    }
}

// ---------------------------------------------------------------------------
extern "C" void kernel_launch(void* const* d_in, const int* in_sizes, int n_in,
                              void* d_out, int out_size)
{
    const float* x    = (const float*)d_in[0];
    const float* filt = (const float*)d_in[1];
    if (n_in >= 2 && in_sizes[0] < in_sizes[1]) {
        x    = (const float*)d_in[1];
        filt = (const float*)d_in[0];
    }
    float* out = (float*)d_out;

    static const int LSZ[9] = {131072, 65537, 32769, 16385, 8193, 4097, 2049, 1025, 513};

    cudaFuncSetAttribute(mid_kernel, cudaFuncAttributeMaxDynamicSharedMemorySize,
                         SM_FLOATS * (int)sizeof(float));

    // forward levels 1..3 (wide)
    for (int l = 1; l <= 3; l++) {
        const int Lout = LSZ[l];
        dim3 grid((Lout + FCH - 1) / FCH, NCH);
        fwd_kernel<<<grid, NTHREADS>>>(x, l);
    }
    // fused middle: fwd 4-8 + inv 7-3
    mid_kernel<<<NCH, FNT, SM_FLOATS * sizeof(float)>>>(filt);
    // inverse levels 2..0 (wide)
    for (int i = 2; i >= 0; i--) {
        const int L    = LSZ[i + 1];
        const int Nout = (i == 0) ? TLEN : 2 * L - 1;
        const int tmax = (Nout + 1) >> 1;
        dim3 grid((tmax + TCH - 1) / TCH, NCH);
        inv_kernel<<<grid, NTHREADS>>>(filt, out, i);
    }
}